// round 13
// baseline (speedup 1.0000x reference)
#include <cuda_runtime.h>
#include <cstdint>

// HamiltonianEvolution: out = q_left_n ⊗ (gate*x) ⊗ conj(q_right_n).
// FFT/IFFT pair is an identity (gate constant along the FFT axis) -> per-
// channel 4x4 linear map.
//
// The kernel is bound by the chip LTS (L2-slice) throughput cap on its
// information-minimum 128 MiB of L2 traffic (three independent designs
// converge at ~7.2 TB/s aggregate). This version amortizes the per-block
// prologue: 16-row tiles, FOUR 16 KB cp.async.bulk stages all issued up
// front by thread 0, consumed in order. Per-thread matrix in 16 regs.

#define QD 256
#define DM 1024
#define TILE_ROWS 16
#define STAGE_ROWS 4
#define NSTAGE 4
#define STAGE_BYTES (STAGE_ROWS * DM * 4)            // 16384
#define SMEM_MBAR 0                                   // 4 mbarriers, 8B each
#define SMEM_BUF 128
#define SMEM_TOTAL (SMEM_BUF + NSTAGE * STAGE_BYTES)  // 65664

__device__ __forceinline__ uint32_t smem_u32(const void* p) {
    uint32_t a;
    asm("{ .reg .u64 t; cvta.to.shared.u64 t, %1; cvt.u32.u64 %0, t; }"
        : "=r"(a) : "l"(p));
    return a;
}
__device__ __forceinline__ void mbar_init(uint32_t mbar, uint32_t count) {
    asm volatile("mbarrier.init.shared.b64 [%0], %1;" :: "r"(mbar), "r"(count) : "memory");
}
__device__ __forceinline__ void mbar_expect_tx(uint32_t mbar, uint32_t bytes) {
    asm volatile("mbarrier.arrive.expect_tx.shared.b64 _, [%0], %1;"
                 :: "r"(mbar), "r"(bytes) : "memory");
}
__device__ __forceinline__ void bulk_g2s(uint32_t dst, const void* src,
                                         uint32_t bytes, uint32_t mbar) {
    asm volatile("cp.async.bulk.shared::cta.global.mbarrier::complete_tx::bytes "
                 "[%0], [%1], %2, [%3];"
                 :: "r"(dst), "l"(src), "r"(bytes), "r"(mbar) : "memory");
}
__device__ __forceinline__ void mbar_wait(uint32_t mbar, uint32_t parity) {
    asm volatile(
        "{\n\t"
        ".reg .pred P;\n\t"
        "WAITLOOP_%=:\n\t"
        "mbarrier.try_wait.parity.acquire.cta.shared::cta.b64 P, [%0], %1, 0x989680;\n\t"
        "@P bra.uni DONE_%=;\n\t"
        "bra.uni WAITLOOP_%=;\n\t"
        "DONE_%=:\n\t"
        "}"
        :: "r"(mbar), "r"(parity) : "memory");
}

__device__ __forceinline__ void build_matrix(const float* __restrict__ q_left,
                                             const float* __restrict__ q_right,
                                             const float* __restrict__ gate,
                                             int j, float m[4][4]) {
    float lw = q_left[0 * QD + j], lx = q_left[1 * QD + j];
    float ly = q_left[2 * QD + j], lz = q_left[3 * QD + j];
    float rw = q_right[0 * QD + j], rx = q_right[1 * QD + j];
    float ry = q_right[2 * QD + j], rz = q_right[3 * QD + j];

    float ln = rsqrtf(lw * lw + lx * lx + ly * ly + lz * lz + 1e-8f);
    lw *= ln; lx *= ln; ly *= ln; lz *= ln;
    float rn = rsqrtf(rw * rw + rx * rx + ry * ry + rz * rz + 1e-8f);
    rw = rw * rn; rx = -rx * rn; ry = -ry * rn; rz = -rz * rn;

    const float g = gate[j];

    // R: p -> p ⊗ rc (rc = conjugated normalized q_right)
    const float R[4][4] = {
        { rw, -rx, -ry, -rz},
        { rx,  rw,  rz, -ry},
        { ry, -rz,  rw,  rx},
        { rz,  ry, -rx,  rw}
    };
    // L: p -> l ⊗ p (l = normalized q_left)
    const float L[4][4] = {
        { lw, -lx, -ly, -lz},
        { lx,  lw, -lz,  ly},
        { ly,  lz,  lw, -lx},
        { lz, -ly,  lx,  lw}
    };

    #pragma unroll
    for (int r = 0; r < 4; r++) {
        #pragma unroll
        for (int c = 0; c < 4; c++) {
            float acc = 0.0f;
            #pragma unroll
            for (int k = 0; k < 4; k++) acc += L[r][k] * R[k][c];
            m[r][c] = g * acc;
        }
    }
}

__global__ __launch_bounds__(256)
void fused_bulk_kernel(const float* __restrict__ q_left,
                       const float* __restrict__ q_right,
                       const float* __restrict__ gate,
                       const float* __restrict__ x,
                       float* __restrict__ out) {
    extern __shared__ char smem[];
    const uint32_t sbase = smem_u32(smem);
    const int j = threadIdx.x;                 // channel 0..255
    const size_t tile_off = (size_t)blockIdx.x * TILE_ROWS * DM;

    if (j == 0) {
        #pragma unroll
        for (int s = 0; s < NSTAGE; s++) mbar_init(sbase + SMEM_MBAR + 8 * s, 1);
    }
    __syncthreads();
    if (j == 0) {
        #pragma unroll
        for (int s = 0; s < NSTAGE; s++) {
            mbar_expect_tx(sbase + SMEM_MBAR + 8 * s, STAGE_BYTES);
            bulk_g2s(sbase + SMEM_BUF + s * STAGE_BYTES,
                     x + tile_off + (size_t)s * STAGE_ROWS * DM,
                     STAGE_BYTES, sbase + SMEM_MBAR + 8 * s);
        }
    }

    // matrix build overlaps the DMA
    float m[4][4];
    build_matrix(q_left, q_right, gate, j, m);

    #pragma unroll
    for (int stage = 0; stage < NSTAGE; stage++) {
        mbar_wait(sbase + SMEM_MBAR + 8 * stage, 0);
        const float* buf = reinterpret_cast<const float*>(
            smem + SMEM_BUF + stage * STAGE_BYTES);
        float* obase = out + tile_off + (size_t)stage * STAGE_ROWS * DM + j;

        #pragma unroll
        for (int r = 0; r < STAGE_ROWS; r++) {
            const float* row = buf + r * DM + j;
            const float i0 = row[0 * QD];
            const float i1 = row[1 * QD];
            const float i2 = row[2 * QD];
            const float i3 = row[3 * QD];

            float o0 = fmaf(m[0][0], i0, fmaf(m[0][1], i1, fmaf(m[0][2], i2, m[0][3] * i3)));
            float o1 = fmaf(m[1][0], i0, fmaf(m[1][1], i1, fmaf(m[1][2], i2, m[1][3] * i3)));
            float o2 = fmaf(m[2][0], i0, fmaf(m[2][1], i1, fmaf(m[2][2], i2, m[2][3] * i3)));
            float o3 = fmaf(m[3][0], i0, fmaf(m[3][1], i1, fmaf(m[3][2], i2, m[3][3] * i3)));

            float* orow = obase + (size_t)r * DM;
            orow[0 * QD] = o0;
            orow[1 * QD] = o1;
            orow[2 * QD] = o2;
            orow[3 * QD] = o3;
        }
    }
}

// ---- generic fallback (any nrows): scalar-channel LDG version ----
__global__ __launch_bounds__(256)
void fused_fallback_kernel(const float* __restrict__ q_left,
                           const float* __restrict__ q_right,
                           const float* __restrict__ gate,
                           const float* __restrict__ x,
                           float* __restrict__ out,
                           int nrows) {
    const int j = threadIdx.x;
    float m[4][4];
    build_matrix(q_left, q_right, gate, j, m);
    const int row = blockIdx.x;
    if (row < nrows) {
        const float* xr = x + (size_t)row * DM + j;
        const float i0 = xr[0 * QD], i1 = xr[1 * QD], i2 = xr[2 * QD], i3 = xr[3 * QD];
        float* orow = out + (size_t)row * DM + j;
        orow[0 * QD] = fmaf(m[0][0], i0, fmaf(m[0][1], i1, fmaf(m[0][2], i2, m[0][3] * i3)));
        orow[1 * QD] = fmaf(m[1][0], i0, fmaf(m[1][1], i1, fmaf(m[1][2], i2, m[1][3] * i3)));
        orow[2 * QD] = fmaf(m[2][0], i0, fmaf(m[2][1], i1, fmaf(m[2][2], i2, m[2][3] * i3)));
        orow[3 * QD] = fmaf(m[3][0], i0, fmaf(m[3][1], i1, fmaf(m[3][2], i2, m[3][3] * i3)));
    }
}

extern "C" void kernel_launch(void* const* d_in, const int* in_sizes, int n_in,
                              void* d_out, int out_size) {
    const float* x    = (const float*)d_in[0];   // (B, T, 1024)
    const float* q_l  = (const float*)d_in[1];   // (4, 256)
    const float* q_r  = (const float*)d_in[2];   // (4, 256)
    const float* gate = (const float*)d_in[3];   // (1,1,1,256)

    const int nrows = in_sizes[0] / DM;          // B*T = 16384

    if (nrows % TILE_ROWS == 0) {
        static bool attr_set = false;
        if (!attr_set) {
            cudaFuncSetAttribute(fused_bulk_kernel,
                                 cudaFuncAttributeMaxDynamicSharedMemorySize,
                                 SMEM_TOTAL);
            attr_set = true;
        }
        const int grid = nrows / TILE_ROWS;      // 1024
        fused_bulk_kernel<<<grid, 256, SMEM_TOTAL>>>(q_l, q_r, gate, x, (float*)d_out);
    } else {
        fused_fallback_kernel<<<nrows, 256>>>(q_l, q_r, gate, x, (float*)d_out, nrows);
    }
}

// round 14
// speedup vs baseline: 1.0014x; 1.0014x over previous
#include <cuda_runtime.h>
#include <cstdint>

// HamiltonianEvolution: out = q_left_n ⊗ (gate*x) ⊗ conj(q_right_n).
// The FFT/IFFT pair in the reference is an identity (the spectral gate is
// constant along the FFT axis), so the op collapses to a per-channel 4x4
// linear map over the information-minimum 128 MiB of traffic.
//
// ROOFLINE NOTE: six structurally distinct implementations (LDG.128 register
// batches, smem-matrix variants, TMA bulk pipelines at occ 21%..79%) all
// converge at 18.5-19.0 us = ~7.2 TB/s aggregate L2 traffic — the B300 LTS
// throughput cap (~6300 B/cyc, path-independent). This is the fastest
// measured configuration: 8-row tiles, two 16 KB cp.async.bulk stages issued
// up front (bytes-in-flight in smem, zero register cost), per-thread 4x4
// matrix in 16 registers, conflict-free LDS.32 + coalesced STG.32.

#define QD 256
#define DM 1024
#define TILE_ROWS 8
#define STAGE_ROWS 4
#define STAGE_BYTES (STAGE_ROWS * DM * 4)   // 16384
#define SMEM_MBAR0 0
#define SMEM_MBAR1 8
#define SMEM_BUF0 128
#define SMEM_BUF1 (SMEM_BUF0 + STAGE_BYTES)
#define SMEM_TOTAL (SMEM_BUF1 + STAGE_BYTES)   // 32896

__device__ __forceinline__ uint32_t smem_u32(const void* p) {
    uint32_t a;
    asm("{ .reg .u64 t; cvta.to.shared.u64 t, %1; cvt.u32.u64 %0, t; }"
        : "=r"(a) : "l"(p));
    return a;
}
__device__ __forceinline__ void mbar_init(uint32_t mbar, uint32_t count) {
    asm volatile("mbarrier.init.shared.b64 [%0], %1;" :: "r"(mbar), "r"(count) : "memory");
}
__device__ __forceinline__ void mbar_expect_tx(uint32_t mbar, uint32_t bytes) {
    asm volatile("mbarrier.arrive.expect_tx.shared.b64 _, [%0], %1;"
                 :: "r"(mbar), "r"(bytes) : "memory");
}
__device__ __forceinline__ void bulk_g2s(uint32_t dst, const void* src,
                                         uint32_t bytes, uint32_t mbar) {
    asm volatile("cp.async.bulk.shared::cta.global.mbarrier::complete_tx::bytes "
                 "[%0], [%1], %2, [%3];"
                 :: "r"(dst), "l"(src), "r"(bytes), "r"(mbar) : "memory");
}
__device__ __forceinline__ void mbar_wait(uint32_t mbar, uint32_t parity) {
    asm volatile(
        "{\n\t"
        ".reg .pred P;\n\t"
        "WAITLOOP_%=:\n\t"
        "mbarrier.try_wait.parity.acquire.cta.shared::cta.b64 P, [%0], %1, 0x989680;\n\t"
        "@P bra.uni DONE_%=;\n\t"
        "bra.uni WAITLOOP_%=;\n\t"
        "DONE_%=:\n\t"
        "}"
        :: "r"(mbar), "r"(parity) : "memory");
}

__device__ __forceinline__ void build_matrix(const float* __restrict__ q_left,
                                             const float* __restrict__ q_right,
                                             const float* __restrict__ gate,
                                             int j, float m[4][4]) {
    float lw = q_left[0 * QD + j], lx = q_left[1 * QD + j];
    float ly = q_left[2 * QD + j], lz = q_left[3 * QD + j];
    float rw = q_right[0 * QD + j], rx = q_right[1 * QD + j];
    float ry = q_right[2 * QD + j], rz = q_right[3 * QD + j];

    float ln = rsqrtf(lw * lw + lx * lx + ly * ly + lz * lz + 1e-8f);
    lw *= ln; lx *= ln; ly *= ln; lz *= ln;
    float rn = rsqrtf(rw * rw + rx * rx + ry * ry + rz * rz + 1e-8f);
    rw = rw * rn; rx = -rx * rn; ry = -ry * rn; rz = -rz * rn;

    const float g = gate[j];

    // R: p -> p ⊗ rc (rc = conjugated normalized q_right)
    const float R[4][4] = {
        { rw, -rx, -ry, -rz},
        { rx,  rw,  rz, -ry},
        { ry, -rz,  rw,  rx},
        { rz,  ry, -rx,  rw}
    };
    // L: p -> l ⊗ p (l = normalized q_left)
    const float L[4][4] = {
        { lw, -lx, -ly, -lz},
        { lx,  lw, -lz,  ly},
        { ly,  lz,  lw, -lx},
        { lz, -ly,  lx,  lw}
    };

    #pragma unroll
    for (int r = 0; r < 4; r++) {
        #pragma unroll
        for (int c = 0; c < 4; c++) {
            float acc = 0.0f;
            #pragma unroll
            for (int k = 0; k < 4; k++) acc += L[r][k] * R[k][c];
            m[r][c] = g * acc;
        }
    }
}

__global__ __launch_bounds__(256)
void fused_bulk_kernel(const float* __restrict__ q_left,
                       const float* __restrict__ q_right,
                       const float* __restrict__ gate,
                       const float* __restrict__ x,
                       float* __restrict__ out) {
    extern __shared__ char smem[];
    const uint32_t sbase = smem_u32(smem);
    const int j = threadIdx.x;                 // channel 0..255
    const size_t tile_off = (size_t)blockIdx.x * TILE_ROWS * DM;

    // Thread 0: init barriers and issue both stage copies immediately
    // (program order suffices for the issuing thread). Other threads only
    // need the init visible before their mbar_wait -> syncthreads below.
    if (j == 0) {
        mbar_init(sbase + SMEM_MBAR0, 1);
        mbar_init(sbase + SMEM_MBAR1, 1);
        mbar_expect_tx(sbase + SMEM_MBAR0, STAGE_BYTES);
        bulk_g2s(sbase + SMEM_BUF0, x + tile_off, STAGE_BYTES, sbase + SMEM_MBAR0);
        mbar_expect_tx(sbase + SMEM_MBAR1, STAGE_BYTES);
        bulk_g2s(sbase + SMEM_BUF1, x + tile_off + (size_t)STAGE_ROWS * DM,
                 STAGE_BYTES, sbase + SMEM_MBAR1);
    }

    // matrix build overlaps the DMA
    float m[4][4];
    build_matrix(q_left, q_right, gate, j, m);

    __syncthreads();   // init visible to all waiters

    #pragma unroll
    for (int stage = 0; stage < 2; stage++) {
        mbar_wait(sbase + (stage == 0 ? SMEM_MBAR0 : SMEM_MBAR1), 0);
        const float* buf = reinterpret_cast<const float*>(
            smem + (stage == 0 ? SMEM_BUF0 : SMEM_BUF1));
        float* obase = out + tile_off + (size_t)stage * STAGE_ROWS * DM + j;

        #pragma unroll
        for (int r = 0; r < STAGE_ROWS; r++) {
            const float* row = buf + r * DM + j;
            const float i0 = row[0 * QD];
            const float i1 = row[1 * QD];
            const float i2 = row[2 * QD];
            const float i3 = row[3 * QD];

            float o0 = fmaf(m[0][0], i0, fmaf(m[0][1], i1, fmaf(m[0][2], i2, m[0][3] * i3)));
            float o1 = fmaf(m[1][0], i0, fmaf(m[1][1], i1, fmaf(m[1][2], i2, m[1][3] * i3)));
            float o2 = fmaf(m[2][0], i0, fmaf(m[2][1], i1, fmaf(m[2][2], i2, m[2][3] * i3)));
            float o3 = fmaf(m[3][0], i0, fmaf(m[3][1], i1, fmaf(m[3][2], i2, m[3][3] * i3)));

            float* orow = obase + (size_t)r * DM;
            orow[0 * QD] = o0;
            orow[1 * QD] = o1;
            orow[2 * QD] = o2;
            orow[3 * QD] = o3;
        }
    }
}

// ---- generic fallback (any nrows): scalar-channel LDG version ----
__global__ __launch_bounds__(256)
void fused_fallback_kernel(const float* __restrict__ q_left,
                           const float* __restrict__ q_right,
                           const float* __restrict__ gate,
                           const float* __restrict__ x,
                           float* __restrict__ out,
                           int nrows) {
    const int j = threadIdx.x;
    float m[4][4];
    build_matrix(q_left, q_right, gate, j, m);
    const int row = blockIdx.x;
    if (row < nrows) {
        const float* xr = x + (size_t)row * DM + j;
        const float i0 = xr[0 * QD], i1 = xr[1 * QD], i2 = xr[2 * QD], i3 = xr[3 * QD];
        float* orow = out + (size_t)row * DM + j;
        orow[0 * QD] = fmaf(m[0][0], i0, fmaf(m[0][1], i1, fmaf(m[0][2], i2, m[0][3] * i3)));
        orow[1 * QD] = fmaf(m[1][0], i0, fmaf(m[1][1], i1, fmaf(m[1][2], i2, m[1][3] * i3)));
        orow[2 * QD] = fmaf(m[2][0], i0, fmaf(m[2][1], i1, fmaf(m[2][2], i2, m[2][3] * i3)));
        orow[3 * QD] = fmaf(m[3][0], i0, fmaf(m[3][1], i1, fmaf(m[3][2], i2, m[3][3] * i3)));
    }
}

extern "C" void kernel_launch(void* const* d_in, const int* in_sizes, int n_in,
                              void* d_out, int out_size) {
    const float* x    = (const float*)d_in[0];   // (B, T, 1024)
    const float* q_l  = (const float*)d_in[1];   // (4, 256)
    const float* q_r  = (const float*)d_in[2];   // (4, 256)
    const float* gate = (const float*)d_in[3];   // (1,1,1,256)

    const int nrows = in_sizes[0] / DM;          // B*T = 16384

    if (nrows % TILE_ROWS == 0) {
        static bool attr_set = false;
        if (!attr_set) {
            cudaFuncSetAttribute(fused_bulk_kernel,
                                 cudaFuncAttributeMaxDynamicSharedMemorySize,
                                 SMEM_TOTAL);
            attr_set = true;
        }
        const int grid = nrows / TILE_ROWS;      // 2048
        fused_bulk_kernel<<<grid, 256, SMEM_TOTAL>>>(q_l, q_r, gate, x, (float*)d_out);
    } else {
        fused_fallback_kernel<<<nrows, 256>>>(q_l, q_r, gate, x, (float*)d_out, nrows);
    }
}

// round 15
// speedup vs baseline: 1.0028x; 1.0014x over previous
#include <cuda_runtime.h>
#include <cstdint>

// HamiltonianEvolution: out = q_left_n ⊗ (gate*x) ⊗ conj(q_right_n).
// The FFT/IFFT pair in the reference is an identity (the spectral gate is
// constant along the FFT axis), so the op collapses to a per-channel 4x4
// linear map over the information-minimum 128 MiB of traffic.
//
// ROOFLINE NOTE (final): seven structurally distinct implementations
// (LDG.128 register batches, smem-matrix variants, TMA bulk pipelines at
// occ 21%..79%, regs 32..119) all converge at 18.4-19.0 us — the machine's
// sustained mixed read/write memory ceiling (~7.3 TB/s aggregate through
// LTS/HBM) on this traffic. This is the fastest measured configuration:
// 8-row tiles, two 16 KB cp.async.bulk stages issued immediately by thread 0
// (bytes-in-flight live in smem at zero register cost), per-thread 4x4
// matrix in 16 registers, conflict-free LDS.32 + coalesced STG.32.

#define QD 256
#define DM 1024
#define TILE_ROWS 8
#define STAGE_ROWS 4
#define STAGE_BYTES (STAGE_ROWS * DM * 4)   // 16384
#define SMEM_MBAR0 0
#define SMEM_MBAR1 8
#define SMEM_BUF0 128
#define SMEM_BUF1 (SMEM_BUF0 + STAGE_BYTES)
#define SMEM_TOTAL (SMEM_BUF1 + STAGE_BYTES)   // 32896

__device__ __forceinline__ uint32_t smem_u32(const void* p) {
    uint32_t a;
    asm("{ .reg .u64 t; cvta.to.shared.u64 t, %1; cvt.u32.u64 %0, t; }"
        : "=r"(a) : "l"(p));
    return a;
}
__device__ __forceinline__ void mbar_init(uint32_t mbar, uint32_t count) {
    asm volatile("mbarrier.init.shared.b64 [%0], %1;" :: "r"(mbar), "r"(count) : "memory");
}
__device__ __forceinline__ void mbar_expect_tx(uint32_t mbar, uint32_t bytes) {
    asm volatile("mbarrier.arrive.expect_tx.shared.b64 _, [%0], %1;"
                 :: "r"(mbar), "r"(bytes) : "memory");
}
__device__ __forceinline__ void bulk_g2s(uint32_t dst, const void* src,
                                         uint32_t bytes, uint32_t mbar) {
    asm volatile("cp.async.bulk.shared::cta.global.mbarrier::complete_tx::bytes "
                 "[%0], [%1], %2, [%3];"
                 :: "r"(dst), "l"(src), "r"(bytes), "r"(mbar) : "memory");
}
__device__ __forceinline__ void mbar_wait(uint32_t mbar, uint32_t parity) {
    asm volatile(
        "{\n\t"
        ".reg .pred P;\n\t"
        "WAITLOOP_%=:\n\t"
        "mbarrier.try_wait.parity.acquire.cta.shared::cta.b64 P, [%0], %1, 0x989680;\n\t"
        "@P bra.uni DONE_%=;\n\t"
        "bra.uni WAITLOOP_%=;\n\t"
        "DONE_%=:\n\t"
        "}"
        :: "r"(mbar), "r"(parity) : "memory");
}

__device__ __forceinline__ void build_matrix(const float* __restrict__ q_left,
                                             const float* __restrict__ q_right,
                                             const float* __restrict__ gate,
                                             int j, float m[4][4]) {
    float lw = q_left[0 * QD + j], lx = q_left[1 * QD + j];
    float ly = q_left[2 * QD + j], lz = q_left[3 * QD + j];
    float rw = q_right[0 * QD + j], rx = q_right[1 * QD + j];
    float ry = q_right[2 * QD + j], rz = q_right[3 * QD + j];

    float ln = rsqrtf(lw * lw + lx * lx + ly * ly + lz * lz + 1e-8f);
    lw *= ln; lx *= ln; ly *= ln; lz *= ln;
    float rn = rsqrtf(rw * rw + rx * rx + ry * ry + rz * rz + 1e-8f);
    rw = rw * rn; rx = -rx * rn; ry = -ry * rn; rz = -rz * rn;

    const float g = gate[j];

    // R: p -> p ⊗ rc (rc = conjugated normalized q_right)
    const float R[4][4] = {
        { rw, -rx, -ry, -rz},
        { rx,  rw,  rz, -ry},
        { ry, -rz,  rw,  rx},
        { rz,  ry, -rx,  rw}
    };
    // L: p -> l ⊗ p (l = normalized q_left)
    const float L[4][4] = {
        { lw, -lx, -ly, -lz},
        { lx,  lw, -lz,  ly},
        { ly,  lz,  lw, -lx},
        { lz, -ly,  lx,  lw}
    };

    #pragma unroll
    for (int r = 0; r < 4; r++) {
        #pragma unroll
        for (int c = 0; c < 4; c++) {
            float acc = 0.0f;
            #pragma unroll
            for (int k = 0; k < 4; k++) acc += L[r][k] * R[k][c];
            m[r][c] = g * acc;
        }
    }
}

__global__ __launch_bounds__(256)
void fused_bulk_kernel(const float* __restrict__ q_left,
                       const float* __restrict__ q_right,
                       const float* __restrict__ gate,
                       const float* __restrict__ x,
                       float* __restrict__ out) {
    extern __shared__ char smem[];
    const uint32_t sbase = smem_u32(smem);
    const int j = threadIdx.x;                 // channel 0..255
    const size_t tile_off = (size_t)blockIdx.x * TILE_ROWS * DM;

    // Thread 0: init barriers and issue both stage copies immediately
    // (program order suffices for the issuing thread). Other threads only
    // need the init visible before their mbar_wait -> syncthreads below.
    if (j == 0) {
        mbar_init(sbase + SMEM_MBAR0, 1);
        mbar_init(sbase + SMEM_MBAR1, 1);
        mbar_expect_tx(sbase + SMEM_MBAR0, STAGE_BYTES);
        bulk_g2s(sbase + SMEM_BUF0, x + tile_off, STAGE_BYTES, sbase + SMEM_MBAR0);
        mbar_expect_tx(sbase + SMEM_MBAR1, STAGE_BYTES);
        bulk_g2s(sbase + SMEM_BUF1, x + tile_off + (size_t)STAGE_ROWS * DM,
                 STAGE_BYTES, sbase + SMEM_MBAR1);
    }

    // matrix build overlaps the DMA
    float m[4][4];
    build_matrix(q_left, q_right, gate, j, m);

    __syncthreads();   // init visible to all waiters

    #pragma unroll
    for (int stage = 0; stage < 2; stage++) {
        mbar_wait(sbase + (stage == 0 ? SMEM_MBAR0 : SMEM_MBAR1), 0);
        const float* buf = reinterpret_cast<const float*>(
            smem + (stage == 0 ? SMEM_BUF0 : SMEM_BUF1));
        float* obase = out + tile_off + (size_t)stage * STAGE_ROWS * DM + j;

        #pragma unroll
        for (int r = 0; r < STAGE_ROWS; r++) {
            const float* row = buf + r * DM + j;
            const float i0 = row[0 * QD];
            const float i1 = row[1 * QD];
            const float i2 = row[2 * QD];
            const float i3 = row[3 * QD];

            float o0 = fmaf(m[0][0], i0, fmaf(m[0][1], i1, fmaf(m[0][2], i2, m[0][3] * i3)));
            float o1 = fmaf(m[1][0], i0, fmaf(m[1][1], i1, fmaf(m[1][2], i2, m[1][3] * i3)));
            float o2 = fmaf(m[2][0], i0, fmaf(m[2][1], i1, fmaf(m[2][2], i2, m[2][3] * i3)));
            float o3 = fmaf(m[3][0], i0, fmaf(m[3][1], i1, fmaf(m[3][2], i2, m[3][3] * i3)));

            float* orow = obase + (size_t)r * DM;
            orow[0 * QD] = o0;
            orow[1 * QD] = o1;
            orow[2 * QD] = o2;
            orow[3 * QD] = o3;
        }
    }
}

// ---- generic fallback (any nrows): scalar-channel LDG version ----
__global__ __launch_bounds__(256)
void fused_fallback_kernel(const float* __restrict__ q_left,
                           const float* __restrict__ q_right,
                           const float* __restrict__ gate,
                           const float* __restrict__ x,
                           float* __restrict__ out,
                           int nrows) {
    const int j = threadIdx.x;
    float m[4][4];
    build_matrix(q_left, q_right, gate, j, m);
    const int row = blockIdx.x;
    if (row < nrows) {
        const float* xr = x + (size_t)row * DM + j;
        const float i0 = xr[0 * QD], i1 = xr[1 * QD], i2 = xr[2 * QD], i3 = xr[3 * QD];
        float* orow = out + (size_t)row * DM + j;
        orow[0 * QD] = fmaf(m[0][0], i0, fmaf(m[0][1], i1, fmaf(m[0][2], i2, m[0][3] * i3)));
        orow[1 * QD] = fmaf(m[1][0], i0, fmaf(m[1][1], i1, fmaf(m[1][2], i2, m[1][3] * i3)));
        orow[2 * QD] = fmaf(m[2][0], i0, fmaf(m[2][1], i1, fmaf(m[2][2], i2, m[2][3] * i3)));
        orow[3 * QD] = fmaf(m[3][0], i0, fmaf(m[3][1], i1, fmaf(m[3][2], i2, m[3][3] * i3)));
    }
}

extern "C" void kernel_launch(void* const* d_in, const int* in_sizes, int n_in,
                              void* d_out, int out_size) {
    const float* x    = (const float*)d_in[0];   // (B, T, 1024)
    const float* q_l  = (const float*)d_in[1];   // (4, 256)
    const float* q_r  = (const float*)d_in[2];   // (4, 256)
    const float* gate = (const float*)d_in[3];   // (1,1,1,256)

    const int nrows = in_sizes[0] / DM;          // B*T = 16384

    if (nrows % TILE_ROWS == 0) {
        static bool attr_set = false;
        if (!attr_set) {
            cudaFuncSetAttribute(fused_bulk_kernel,
                                 cudaFuncAttributeMaxDynamicSharedMemorySize,
                                 SMEM_TOTAL);
            attr_set = true;
        }
        const int grid = nrows / TILE_ROWS;      // 2048
        fused_bulk_kernel<<<grid, 256, SMEM_TOTAL>>>(q_l, q_r, gate, x, (float*)d_out);
    } else {
        fused_fallback_kernel<<<nrows, 256>>>(q_l, q_r, gate, x, (float*)d_out, nrows);
    }
}